// round 10
// baseline (speedup 1.0000x reference)
#include <cuda_runtime.h>
#include <cstdint>

#define GRID_DIM   128
#define U_PIX      8192
#define N_TRK      3000
#define M_NEIGH    16
#define T_SIG      400
#define ADC_SAMPLE 50
#define NBINS      200          // T_TOTAL / ADC_SAMPLE
#define MAX_BINS   9            // ceil((400+49)/50)
#define GAIN       0.25f
#define PEDESTAL   74.0f
#define ADC_MAX    255.0f

// Scratch (allocation-free rule: __device__ globals)
// g_lut is NEVER invalidated: k_accum verifies each hit against unique_pix.
__device__ int   g_lut[GRID_DIM * GRID_DIM];     // (y,x) -> candidate pixel id
__device__ float g_acc[U_PIX * NBINS];           // per-pixel per-bin sums

// ---------------------------------------------------------------------------
// Kernel 1: LUT scatter only (zeroing of g_acc is a memset node in the graph)
// ---------------------------------------------------------------------------
__global__ void k_prep(const int2* __restrict__ unique_pix) {
    int tid = blockIdx.x * blockDim.x + threadIdx.x;
    if (tid < U_PIX) {
        int2 c = unique_pix[tid];
        g_lut[c.x * GRID_DIM + c.y] = tid;
    }
}

// ---------------------------------------------------------------------------
// Window accumulate helper. BASE = warp-uniform global bin of the window's
// first sample (compile-time per branch arm). q = within-bin position of this
// lane's first chunk element (BASE*50 + q == rel position of element 0).
// Adds the chunk's lo/hi split into v[BASE + k0] / v[BASE + k0 + 1].
// Compile-time guards drop targets > 8; droppable targets provably get 0.
// ---------------------------------------------------------------------------
template<int BASE>
__device__ __forceinline__ void win_acc(float (&v)[MAX_BINS], float4 f,
                                        int q, bool valid) {
    float s01 = f.x + f.y, s012 = s01 + f.z, s0123 = s012 + f.w;
    int k0 = q / 50;                      // local bin of first elem (0..3)
    int k1 = (q + 3) / 50;                // local bin of last elem
    float lo, hi;
    if (k1 == k0) { lo = s0123; hi = 0.0f; }
    else {
        int r = 50 * k1 - q;              // elems in lower bin: 1..3
        lo = (r == 1) ? f.x : ((r == 2) ? s01 : s012);
        hi = s0123 - lo;
    }
    if (!valid) { lo = 0.0f; hi = 0.0f; k0 = 0; }
    #pragma unroll
    for (int i = 0; i < 4; ++i) {
        if (BASE + i <= 8)     { if (k0 == i) v[BASE + i]     += lo; }
        if (BASE + i + 1 <= 8) { if (k0 == i) v[BASE + i + 1] += hi; }
    }
}

// ---------------------------------------------------------------------------
// Kernel 2: one warp per (track, neighbor) pair.
// 4 coalesced LDG.128 per warp (vs 36 scalar LDG). rel0 is warp-uniform, so
// each 128-sample window's base bin has only 2 possible values -> uniform
// branch into arms with COMPILE-TIME bin targets; per-lane residual is a
// 0..3 predicated offset. Combine = proven 9-wide butterfly + 9 REDGs.
// ---------------------------------------------------------------------------
__global__ void k_accum(const int2*  __restrict__ neigh,
                        const int2*  __restrict__ upix,
                        const float* __restrict__ sig,
                        const int*   __restrict__ starts) {
    int gwarp = (blockIdx.x * blockDim.x + threadIdx.x) >> 5;
    int lane  = threadIdx.x & 31;
    if (gwarp >= N_TRK * M_NEIGH) return;

    int2 c = neigh[gwarp];
    if (c.x < 0) return;                          // dead channel -> discard

    int  pid = g_lut[c.x * GRID_DIM + c.y];       // candidate (may be stale)
    int2 u   = upix[pid];
    if (u.x != c.x || u.y != c.y) return;         // verify: reject stale/no-match

    int start = starts[gwarp >> 4];               // M_NEIGH = 16
    int b0    = start / ADC_SAMPLE;               // 0..191
    int rel0  = start - b0 * ADC_SAMPLE;          // 0..49 (warp-uniform)

    const float4* s4 = reinterpret_cast<const float4*>(sig + (size_t)gwarp * T_SIG);

    // 4 coalesced vector loads, issued up front (streaming: read-once data)
    float4 f0 = __ldcs(s4 + lane);                //  chunks  0..31
    float4 f1 = __ldcs(s4 + 32 + lane);           //  chunks 32..63
    float4 f2 = __ldcs(s4 + 64 + lane);           //  chunks 64..95
    float4 f3 = (lane < 4) ? __ldcs(s4 + 96 + lane)
                           : make_float4(0.f, 0.f, 0.f, 0.f);  // chunks 96..99

    float v[MAX_BINS];
    #pragma unroll
    for (int i = 0; i < MAX_BINS; ++i) v[i] = 0.0f;

    int q = 4 * lane;
    // window 0: samples [0,128),   base bin (rel0+0)/50   == 0 always
    win_acc<0>(v, f0, rel0 + q, true);
    // window 1: samples [128,256), base bin (rel0+128)/50 == 2 or 3
    if (rel0 < 22) win_acc<2>(v, f1, rel0 + 28 + q, true);
    else           win_acc<3>(v, f1, rel0 - 22 + q, true);
    // window 2: samples [256,384), base bin (rel0+256)/50 == 5 or 6
    if (rel0 < 44) win_acc<5>(v, f2, rel0 + 6 + q, true);
    else           win_acc<6>(v, f2, rel0 - 44 + q, true);
    // window 3: samples [384,400), base bin (rel0+384)/50 == 7 or 8 (4 chunks)
    if (rel0 < 16) win_acc<7>(v, f3, rel0 + 34 + q, lane < 4);
    else           win_acc<8>(v, f3, rel0 - 16 + q, lane < 4);

    // One butterfly over the 9-vector: 5 stages, 9 independent adds per stage
    #pragma unroll
    for (int o = 16; o > 0; o >>= 1) {
        #pragma unroll
        for (int i = 0; i < MAX_BINS; ++i)
            v[i] += __shfl_xor_sync(0xffffffffu, v[i], o);
    }

    float mine = 0.0f;
    #pragma unroll
    for (int i = 0; i < MAX_BINS; ++i)
        if (lane == i) mine = v[i];

    if (lane < MAX_BINS)                          // b0+8 <= 199 always
        atomicAdd(&g_acc[(size_t)pid * NBINS + b0 + lane], mine);
}

// ---------------------------------------------------------------------------
// Kernel 3: TWO rows per warp.  [R6/R9 body, proven best]
// ---------------------------------------------------------------------------
__global__ void k_final(float* __restrict__ out) {
    int gwarp = (blockIdx.x * blockDim.x + threadIdx.x) >> 5;  // 0..4095
    int lane  = threadIdx.x & 31;
    if (gwarp >= U_PIX / 2) return;

    int rowA = gwarp * 2, rowB = rowA + 1;
    const float4* a4 = reinterpret_cast<const float4*>(g_acc + (size_t)rowA * NBINS);
    const float4* b4 = reinterpret_cast<const float4*>(g_acc + (size_t)rowB * NBINS);
    float4* oa4 = reinterpret_cast<float4*>(out + (size_t)rowA * NBINS);
    float4* ob4 = reinterpret_cast<float4*>(out + (size_t)rowB * NBINS);

    const float4 z4 = make_float4(0.f, 0.f, 0.f, 0.f);
    bool act1 = (lane < NBINS / 4 - 32);          // lanes 0..17

    float4 xa0 = a4[lane];
    float4 xb0 = b4[lane];
    float4 xa1 = act1 ? a4[32 + lane] : z4;
    float4 xb1 = act1 ? b4[32 + lane] : z4;

    xa0.y += xa0.x;  xa0.z += xa0.y;  xa0.w += xa0.z;
    xa1.y += xa1.x;  xa1.z += xa1.y;  xa1.w += xa1.z;
    xb0.y += xb0.x;  xb0.z += xb0.y;  xb0.w += xb0.z;
    xb1.y += xb1.x;  xb1.z += xb1.y;  xb1.w += xb1.z;
    float sa0 = xa0.w, sa1 = xa1.w, sb0 = xb0.w, sb1 = xb1.w;

    float ia0 = sa0, ia1 = sa1, ib0 = sb0, ib1 = sb1;
    #pragma unroll
    for (int o = 1; o < 32; o <<= 1) {
        float ua0 = __shfl_up_sync(0xffffffffu, ia0, o);
        float ua1 = __shfl_up_sync(0xffffffffu, ia1, o);
        float ub0 = __shfl_up_sync(0xffffffffu, ib0, o);
        float ub1 = __shfl_up_sync(0xffffffffu, ib1, o);
        if (lane >= o) { ia0 += ua0; ia1 += ua1; ib0 += ub0; ib1 += ub1; }
    }
    float totA0 = __shfl_sync(0xffffffffu, ia0, 31);
    float totB0 = __shfl_sync(0xffffffffu, ib0, 31);
    float baseA0 = ia0 - sa0;
    float baseA1 = totA0 + (ia1 - sa1);
    float baseB0 = ib0 - sb0;
    float baseB1 = totB0 + (ib1 - sb1);

    float4 r;
    #define ADCV(x, b) fminf(fmaxf(((x) + (b)) * GAIN + PEDESTAL, 0.0f), ADC_MAX)
    r.x = ADCV(xa0.x, baseA0); r.y = ADCV(xa0.y, baseA0);
    r.z = ADCV(xa0.z, baseA0); r.w = ADCV(xa0.w, baseA0);
    oa4[lane] = r;
    r.x = ADCV(xb0.x, baseB0); r.y = ADCV(xb0.y, baseB0);
    r.z = ADCV(xb0.z, baseB0); r.w = ADCV(xb0.w, baseB0);
    ob4[lane] = r;
    if (act1) {
        r.x = ADCV(xa1.x, baseA1); r.y = ADCV(xa1.y, baseA1);
        r.z = ADCV(xa1.z, baseA1); r.w = ADCV(xa1.w, baseA1);
        oa4[32 + lane] = r;
        r.x = ADCV(xb1.x, baseB1); r.y = ADCV(xb1.y, baseB1);
        r.z = ADCV(xb1.z, baseB1); r.w = ADCV(xb1.w, baseB1);
        ob4[32 + lane] = r;
    }
    #undef ADCV
}

// ---------------------------------------------------------------------------
// Launch: memset node + 3 kernels
// ---------------------------------------------------------------------------
extern "C" void kernel_launch(void* const* d_in, const int* in_sizes, int n_in,
                              void* d_out, int out_size) {
    const int2*  neigh  = (const int2*) d_in[0];   // (3000, 16, 2) int32
    const int2*  upix   = (const int2*) d_in[1];   // (8192, 2) int32
    const float* sig    = (const float*)d_in[2];   // (3000, 16, 400) float32
    const int*   starts = (const int*)  d_in[3];   // (3000,) int32
    float*       out    = (float*)      d_out;     // (8192, 200) float32

    (void)in_sizes; (void)n_in; (void)out_size;

    void* acc_ptr = nullptr;
    cudaGetSymbolAddress(&acc_ptr, g_acc);
    cudaMemsetAsync(acc_ptr, 0, (size_t)U_PIX * NBINS * sizeof(float), 0);

    k_prep<<<(U_PIX + 255) / 256, 256>>>(upix);

    {
        int total_warps = N_TRK * M_NEIGH;         // 48000
        int threads = 256;
        int blocks  = (total_warps * 32 + threads - 1) / threads;
        k_accum<<<blocks, threads>>>(neigh, upix, sig, starts);
    }
    {
        int warps   = U_PIX / 2;                   // 4096
        int threads = 256;
        int blocks  = (warps * 32 + threads - 1) / threads;   // 512
        k_final<<<blocks, threads>>>(out);
    }
}

// round 11
// speedup vs baseline: 1.0107x; 1.0107x over previous
#include <cuda_runtime.h>
#include <cstdint>

#define GRID_DIM   128
#define U_PIX      8192
#define N_TRK      3000
#define M_NEIGH    16
#define T_SIG      400
#define ADC_SAMPLE 50
#define NBINS      200          // T_TOTAL / ADC_SAMPLE
#define MAX_BINS   9            // ceil((400+49)/50)
#define GAIN       0.25f
#define PEDESTAL   74.0f
#define ADC_MAX    255.0f

// Scratch (allocation-free rule: __device__ globals)
// g_lut is NEVER invalidated: k_accum verifies each hit against unique_pix.
__device__ int   g_lut[GRID_DIM * GRID_DIM];     // (y,x) -> candidate pixel id
__device__ float g_acc[U_PIX * NBINS];           // per-pixel per-bin sums

// ---------------------------------------------------------------------------
// Kernel 1: LUT scatter only (zeroing of g_acc is a memset node in the graph)
// ---------------------------------------------------------------------------
__global__ void k_prep(const int2* __restrict__ unique_pix) {
    int tid = blockIdx.x * blockDim.x + threadIdx.x;
    if (tid < U_PIX) {
        int2 c = unique_pix[tid];
        g_lut[c.x * GRID_DIM + c.y] = tid;
    }
}

// ---------------------------------------------------------------------------
// Kernel 2: one warp per (track, neighbor) pair.  [R9 body — FROZEN.
// Five restructurings (R3/R4/R5/R8/R10) all measured slower than this.]
// 18 segment loads up front (MLP 18), one 5-stage butterfly over the
// 9-register bin vector (full ILP), lanes 0..8 flush with one REDG each.
// ---------------------------------------------------------------------------
__global__ void k_accum(const int2*  __restrict__ neigh,
                        const int2*  __restrict__ upix,
                        const float* __restrict__ sig,
                        const int*   __restrict__ starts) {
    int gwarp = (blockIdx.x * blockDim.x + threadIdx.x) >> 5;
    int lane  = threadIdx.x & 31;
    if (gwarp >= N_TRK * M_NEIGH) return;

    int2 c = neigh[gwarp];
    if (c.x < 0) return;                          // dead channel -> discard

    int  pid = g_lut[c.x * GRID_DIM + c.y];       // candidate (may be stale)
    int2 u   = upix[pid];
    if (u.x != c.x || u.y != c.y) return;         // verify: reject stale/no-match

    int start = starts[gwarp >> 4];               // M_NEIGH = 16
    int b0    = start / ADC_SAMPLE;               // 0..191
    int rel0  = start - b0 * ADC_SAMPLE;          // 0..49

    const float* s = sig + (size_t)gwarp * T_SIG;

    float v[MAX_BINS];
    #pragma unroll
    for (int i = 0; i < MAX_BINS; ++i) {
        int lo = i * ADC_SAMPLE - rel0;           if (lo < 0)     lo = 0;
        int hi = (i + 1) * ADC_SAMPLE - rel0;     if (hi > T_SIG) hi = T_SIG;
        int t  = lo + lane;
        float a = (t      < hi) ? s[t]      : 0.0f;
        float b = (t + 32 < hi) ? s[t + 32] : 0.0f;  // segment length <= 50
        v[i] = a + b;
    }

    #pragma unroll
    for (int o = 16; o > 0; o >>= 1) {
        #pragma unroll
        for (int i = 0; i < MAX_BINS; ++i)
            v[i] += __shfl_xor_sync(0xffffffffu, v[i], o);
    }

    float mine = 0.0f;
    #pragma unroll
    for (int i = 0; i < MAX_BINS; ++i)
        if (lane == i) mine = v[i];

    if (lane < MAX_BINS)                          // b0+8 <= 199 always
        atomicAdd(&g_acc[(size_t)pid * NBINS + b0 + lane], mine);
}

// ---------------------------------------------------------------------------
// Kernel 3: FOUR rows per warp. 8 chunk loads issued up front (MLP 8, all L2
// hits); EIGHT warp scans interleaved in ONE 5-stage shuffle chain; fused
// affine+clip; vectorized writes.
// ---------------------------------------------------------------------------
__global__ void k_final(float* __restrict__ out) {
    int gwarp = (blockIdx.x * blockDim.x + threadIdx.x) >> 5;  // 0..2047
    int lane  = threadIdx.x & 31;
    if (gwarp >= U_PIX / 4) return;

    const float4 z4 = make_float4(0.f, 0.f, 0.f, 0.f);
    bool act1 = (lane < NBINS / 4 - 32);          // lanes 0..17

    const float4* rp[4];
    float4*       op[4];
    float4 x[4][2];
    #pragma unroll
    for (int r = 0; r < 4; ++r) {
        int row = gwarp * 4 + r;
        rp[r] = reinterpret_cast<const float4*>(g_acc + (size_t)row * NBINS);
        op[r] = reinterpret_cast<float4*>(out + (size_t)row * NBINS);
        x[r][0] = rp[r][lane];
        x[r][1] = act1 ? rp[r][32 + lane] : z4;
    }

    float s[4][2], inc[4][2];
    #pragma unroll
    for (int r = 0; r < 4; ++r) {
        #pragma unroll
        for (int ch = 0; ch < 2; ++ch) {
            x[r][ch].y += x[r][ch].x;
            x[r][ch].z += x[r][ch].y;
            x[r][ch].w += x[r][ch].z;
            s[r][ch]   = x[r][ch].w;
            inc[r][ch] = s[r][ch];
        }
    }

    // 8 interleaved warp inclusive scans, one shared 5-stage chain
    #pragma unroll
    for (int o = 1; o < 32; o <<= 1) {
        float u[4][2];
        #pragma unroll
        for (int r = 0; r < 4; ++r) {
            u[r][0] = __shfl_up_sync(0xffffffffu, inc[r][0], o);
            u[r][1] = __shfl_up_sync(0xffffffffu, inc[r][1], o);
        }
        if (lane >= o) {
            #pragma unroll
            for (int r = 0; r < 4; ++r) { inc[r][0] += u[r][0]; inc[r][1] += u[r][1]; }
        }
    }

    #define ADCV(xv, b) fminf(fmaxf(((xv) + (b)) * GAIN + PEDESTAL, 0.0f), ADC_MAX)
    #pragma unroll
    for (int r = 0; r < 4; ++r) {
        float tot0  = __shfl_sync(0xffffffffu, inc[r][0], 31);
        float base0 = inc[r][0] - s[r][0];
        float base1 = tot0 + (inc[r][1] - s[r][1]);

        float4 o0;
        o0.x = ADCV(x[r][0].x, base0); o0.y = ADCV(x[r][0].y, base0);
        o0.z = ADCV(x[r][0].z, base0); o0.w = ADCV(x[r][0].w, base0);
        op[r][lane] = o0;
        if (act1) {
            float4 o1;
            o1.x = ADCV(x[r][1].x, base1); o1.y = ADCV(x[r][1].y, base1);
            o1.z = ADCV(x[r][1].z, base1); o1.w = ADCV(x[r][1].w, base1);
            op[r][32 + lane] = o1;
        }
    }
    #undef ADCV
}

// ---------------------------------------------------------------------------
// Launch: memset node + 3 kernels
// ---------------------------------------------------------------------------
extern "C" void kernel_launch(void* const* d_in, const int* in_sizes, int n_in,
                              void* d_out, int out_size) {
    const int2*  neigh  = (const int2*) d_in[0];   // (3000, 16, 2) int32
    const int2*  upix   = (const int2*) d_in[1];   // (8192, 2) int32
    const float* sig    = (const float*)d_in[2];   // (3000, 16, 400) float32
    const int*   starts = (const int*)  d_in[3];   // (3000,) int32
    float*       out    = (float*)      d_out;     // (8192, 200) float32

    (void)in_sizes; (void)n_in; (void)out_size;

    void* acc_ptr = nullptr;
    cudaGetSymbolAddress(&acc_ptr, g_acc);
    cudaMemsetAsync(acc_ptr, 0, (size_t)U_PIX * NBINS * sizeof(float), 0);

    k_prep<<<(U_PIX + 255) / 256, 256>>>(upix);

    {
        int total_warps = N_TRK * M_NEIGH;         // 48000
        int threads = 256;
        int blocks  = (total_warps * 32 + threads - 1) / threads;
        k_accum<<<blocks, threads>>>(neigh, upix, sig, starts);
    }
    {
        int warps   = U_PIX / 4;                   // 2048
        int threads = 256;
        int blocks  = (warps * 32 + threads - 1) / threads;   // 256
        k_final<<<blocks, threads>>>(out);
    }
}